// round 1
// baseline (speedup 1.0000x reference)
#include <cuda_runtime.h>
#include <math.h>
#include <stdint.h>

// Problem constants
#define Bp 4
#define Np 2048
#define Cp 512
#define Hp 8
#define Dp 64
#define Wp 4
#define NWp 512
#define KEEP 64

// Scratch (device globals; no allocation allowed)
__device__ float g_q[Bp*Hp*Np*Dp];       // [B,H,N,D]
__device__ float g_k[Bp*Hp*Np*Dp];
__device__ float g_v[Bp*Hp*Np*Dp];
__device__ float g_attn[Bp*Np*Hp*Dp];    // [B,N,H*D]
__device__ int   g_idx[Bp*Hp*NWp*KEEP];  // [B,H,NW,64]

// ---------------------------------------------------------------------------
// GEMM 1: qkv = x @ Wqkv + bqkv, epilogue scatters into g_q/g_k/g_v
// M=8192 (B*N), Nn=1536 (H*D*3), K=512. Classic 128x128x8 SGEMM, 256 threads.
// ---------------------------------------------------------------------------
__global__ __launch_bounds__(256) void gemm_qkv_kernel(
    const float* __restrict__ A,      // x [8192,512]
    const float* __restrict__ Bw,     // Wqkv [512,1536]
    const float* __restrict__ bias)   // bqkv [1536]
{
    const int M = Bp*Np, Nn = 3*Hp*Dp, Kk = Cp;
    __shared__ float As[8][128];
    __shared__ float Bs[8][128];
    int tid = threadIdx.x;
    int tx = tid & 15, ty = tid >> 4;
    int bx = blockIdx.x, by = blockIdx.y;

    int arow = by*128 + (tid >> 1);
    int acol0 = (tid & 1) * 4;
    int brow0 = tid >> 5;
    int bcol  = bx*128 + (tid & 31) * 4;

    float acc[8][8];
    #pragma unroll
    for (int i = 0; i < 8; i++)
        #pragma unroll
        for (int j = 0; j < 8; j++) acc[i][j] = 0.f;

    for (int k0 = 0; k0 < Kk; k0 += 8) {
        float4 a = *(const float4*)(A + (size_t)arow*Kk + k0 + acol0);
        As[acol0+0][tid>>1] = a.x;
        As[acol0+1][tid>>1] = a.y;
        As[acol0+2][tid>>1] = a.z;
        As[acol0+3][tid>>1] = a.w;
        float4 b = *(const float4*)(Bw + (size_t)(k0 + brow0)*Nn + bcol);
        *(float4*)&Bs[brow0][(tid & 31)*4] = b;
        __syncthreads();
        #pragma unroll
        for (int kk = 0; kk < 8; kk++) {
            float ra[8], rb[8];
            *(float4*)&ra[0] = *(const float4*)&As[kk][ty*8];
            *(float4*)&ra[4] = *(const float4*)&As[kk][ty*8+4];
            *(float4*)&rb[0] = *(const float4*)&Bs[kk][tx*8];
            *(float4*)&rb[4] = *(const float4*)&Bs[kk][tx*8+4];
            #pragma unroll
            for (int i = 0; i < 8; i++)
                #pragma unroll
                for (int j = 0; j < 8; j++)
                    acc[i][j] += ra[i]*rb[j];
        }
        __syncthreads();
    }
    // Epilogue: scatter c -> (h,d,s): s=c%3, hd=c/3
    #pragma unroll
    for (int i = 0; i < 8; i++) {
        int m = by*128 + ty*8 + i;
        int b = m >> 11, nn = m & (Np-1);
        #pragma unroll
        for (int j = 0; j < 8; j++) {
            int c = bx*128 + tx*8 + j;
            float v = acc[i][j] + bias[c];
            int s = c % 3;
            int hd = c / 3;
            int h = hd >> 6, d = hd & 63;
            float* dst = (s == 0) ? g_q : (s == 1) ? g_k : g_v;
            dst[(((size_t)(b*Hp + h))*Np + nn)*Dp + d] = v;
        }
    }
}

// ---------------------------------------------------------------------------
// Selection: per (b,h,nw), radix-select 64 smallest of noised[j], stable
// in-index-order emit -> indices come out already sorted ascending.
// gridDim = B*H*NW = 16384, 256 threads, 8 candidates/thread.
// ---------------------------------------------------------------------------
__global__ __launch_bounds__(256) void select_kernel(
    const float* __restrict__ pareto,        // [B,H,NW,N]
    const unsigned char* __restrict__ mask)  // [B,N] bool
{
    __shared__ unsigned int skey[2048];
    __shared__ unsigned int hist[256];
    __shared__ unsigned int sLess[256], sEq[256];
    __shared__ unsigned int sPrefix, sR;

    int p = blockIdx.x;                   // (b*H + h)*NW + nw
    int nw = p & (NWp-1);
    int b  = p / (Hp*NWp);
    int t  = threadIdx.x;

    const float* prow = pareto + (size_t)p * Np;
    const unsigned char* mrow = mask + (size_t)b * Np;

    // Build order-preserving uint keys
    #pragma unroll
    for (int v = 0; v < 2; v++) {
        int j0 = t*8 + v*4;
        float4 nz = *(const float4*)(prow + j0);
        float noise[4] = {nz.x, nz.y, nz.z, nz.w};
        #pragma unroll
        for (int i = 0; i < 4; i++) {
            int j = j0 + i;
            int cj = j >> 2;
            float gridv = fabsf((float)(nw - cj));
            float val = gridv - noise[i];
            if (mrow[j]) val = 3.402823466e38f;
            unsigned ub = __float_as_uint(val);
            ub ^= (ub & 0x80000000u) ? 0xFFFFFFFFu : 0x80000000u;
            skey[j] = ub;
        }
    }

    // Radix select: find key of rank 63 (0-based) ascending
    unsigned prefix = 0;
    for (int pass = 3; pass >= 0; --pass) {
        hist[t] = 0;
        __syncthreads();
        unsigned hm = (pass == 3) ? 0u : (0xFFFFFFFFu << ((pass+1)*8));
        unsigned r = (pass == 3) ? 64u : sR;
        #pragma unroll
        for (int i = 0; i < 8; i++) {
            unsigned k = skey[t*8 + i];
            if ((k & hm) == prefix)
                atomicAdd(&hist[(k >> (pass*8)) & 0xFF], 1u);
        }
        __syncthreads();
        if (t == 0) {
            unsigned cum = 0; int d = 0;
            for (; d < 256; ++d) {
                if (cum + hist[d] >= r) break;
                cum += hist[d];
            }
            sPrefix = prefix | ((unsigned)d << (pass*8));
            sR = r - cum;
        }
        __syncthreads();
        prefix = sPrefix;
        __syncthreads();
    }
    unsigned T = prefix;

    // Stable keep-scan: count (<T) and (==T) per thread, block scan
    unsigned lessC = 0, eqC = 0;
    #pragma unroll
    for (int i = 0; i < 8; i++) {
        unsigned k = skey[t*8 + i];
        lessC += (k < T);
        eqC   += (k == T);
    }
    sLess[t] = lessC; sEq[t] = eqC;
    __syncthreads();
    for (int off = 1; off < 256; off <<= 1) {
        unsigned l = (t >= off) ? sLess[t-off] : 0u;
        unsigned e = (t >= off) ? sEq[t-off]   : 0u;
        __syncthreads();
        sLess[t] += l; sEq[t] += e;
        __syncthreads();
    }
    unsigned totalLess = sLess[255];
    unsigned lb = sLess[t] - lessC;     // exclusive prefix
    unsigned eb = sEq[t]   - eqC;
    unsigned rr = 64u - totalLess;      // tie quota

    int* oidx = g_idx + (size_t)p * KEEP;
    #pragma unroll
    for (int i = 0; i < 8; i++) {
        int j = t*8 + i;
        unsigned k = skey[j];
        if (k < T) {
            oidx[lb + min(eb, rr)] = j;
            lb++;
        } else if (k == T) {
            if (eb < rr) oidx[lb + eb] = j;
            eb++;
        }
    }
}

// ---------------------------------------------------------------------------
// Attention: one block per (b,h,nw); gather K/V rows, dots+pb, softmax, AV.
// 128 threads.
// ---------------------------------------------------------------------------
__global__ __launch_bounds__(128) void attn_kernel(
    const float* __restrict__ pos_bias,      // [H,N,N]
    const unsigned char* __restrict__ mask)  // [B,N]
{
    __shared__ int   sidx[KEEP];
    __shared__ float ks[KEEP][65];
    __shared__ float vs[KEEP][65];
    __shared__ float qs[Wp][Dp];
    __shared__ float sd[Wp][68];

    int p  = blockIdx.x;                 // (b*H + h)*NW + nw
    int nw = p & (NWp-1);
    int bh = p >> 9;                     // b*H + h
    int h  = bh & (Hp-1);
    int b  = bh >> 3;
    int t  = threadIdx.x;

    if (t < KEEP) sidx[t] = g_idx[(size_t)p * KEEP + t];
    if (t >= 64 && t < 128) {
        int d = t - 64;
        #pragma unroll
        for (int w = 0; w < Wp; w++)
            qs[w][d] = g_q[((size_t)bh*Np + nw*Wp + w)*Dp + d];
    }
    __syncthreads();

    // Gather K/V: 2 threads per key row (32 floats each)
    {
        int z = t >> 1, half = t & 1;
        int row = sidx[z];
        const float* kp = g_k + ((size_t)bh*Np + row)*Dp + half*32;
        const float* vp = g_v + ((size_t)bh*Np + row)*Dp + half*32;
        #pragma unroll
        for (int i = 0; i < 8; i++) {
            float4 kv = *(const float4*)(kp + i*4);
            int c = half*32 + i*4;
            ks[z][c+0] = kv.x; ks[z][c+1] = kv.y; ks[z][c+2] = kv.z; ks[z][c+3] = kv.w;
            float4 vv = *(const float4*)(vp + i*4);
            vs[z][c+0] = vv.x; vs[z][c+1] = vv.y; vs[z][c+2] = vv.z; vs[z][c+3] = vv.w;
        }
    }
    __syncthreads();

    // Dots + pos_bias + masking
    const float scale = 0.125f;  // D^-0.5
    #pragma unroll
    for (int pr = t; pr < Wp*KEEP; pr += 128) {
        int w = pr >> 6, z = pr & 63;
        float acc = 0.f;
        #pragma unroll
        for (int d = 0; d < Dp; d++) acc += qs[w][d] * ks[z][d];
        int key = sidx[z];
        float pb = pos_bias[((size_t)h*Np + nw*Wp + w)*Np + key];
        float val = acc*scale + pb;
        bool qm = mask[(size_t)b*Np + nw*Wp + w] != 0;
        bool km = mask[(size_t)b*Np + key] != 0;
        if (qm && km) val = -3.402823466e38f;
        sd[w][z] = val;
    }
    __syncthreads();

    // Softmax: warp w owns row w (64 entries, 2 per lane)
    {
        int w = t >> 5, lane = t & 31;
        float v0 = sd[w][lane], v1 = sd[w][lane+32];
        float m = fmaxf(v0, v1);
        #pragma unroll
        for (int off = 16; off > 0; off >>= 1)
            m = fmaxf(m, __shfl_xor_sync(0xffffffffu, m, off));
        float e0 = __expf(v0 - m), e1 = __expf(v1 - m);
        float s = e0 + e1;
        #pragma unroll
        for (int off = 16; off > 0; off >>= 1)
            s += __shfl_xor_sync(0xffffffffu, s, off);
        float inv = 1.f / s;
        sd[w][lane]    = e0*inv;
        sd[w][lane+32] = e1*inv;
    }
    __syncthreads();

    // AV: out[w][d] = sum_z attn[w][z] * v[z][d]
    #pragma unroll
    for (int pr = t; pr < Wp*Dp; pr += 128) {
        int w = pr >> 6, d = pr & 63;
        float acc = 0.f;
        #pragma unroll
        for (int z = 0; z < KEEP; z++) acc += sd[w][z] * vs[z][d];
        g_attn[((size_t)b*Np + nw*Wp + w)*(Hp*Dp) + h*Dp + d] = acc;
    }
}

// ---------------------------------------------------------------------------
// GEMM 2: out = g_attn @ Wo + bo. M=8192, Nn=512, K=512.
// ---------------------------------------------------------------------------
__global__ __launch_bounds__(256) void gemm_out_kernel(
    const float* __restrict__ Bw,     // Wo [512,512]
    const float* __restrict__ bias,   // bo [512]
    float* __restrict__ Cout)         // [8192,512]
{
    const int Nn = Cp, Kk = Hp*Dp;
    __shared__ float As[8][128];
    __shared__ float Bs[8][128];
    int tid = threadIdx.x;
    int tx = tid & 15, ty = tid >> 4;
    int bx = blockIdx.x, by = blockIdx.y;

    int arow = by*128 + (tid >> 1);
    int acol0 = (tid & 1) * 4;
    int brow0 = tid >> 5;
    int bcol  = bx*128 + (tid & 31) * 4;

    float acc[8][8];
    #pragma unroll
    for (int i = 0; i < 8; i++)
        #pragma unroll
        for (int j = 0; j < 8; j++) acc[i][j] = 0.f;

    for (int k0 = 0; k0 < Kk; k0 += 8) {
        float4 a = *(const float4*)(g_attn + (size_t)arow*Kk + k0 + acol0);
        As[acol0+0][tid>>1] = a.x;
        As[acol0+1][tid>>1] = a.y;
        As[acol0+2][tid>>1] = a.z;
        As[acol0+3][tid>>1] = a.w;
        float4 b = *(const float4*)(Bw + (size_t)(k0 + brow0)*Nn + bcol);
        *(float4*)&Bs[brow0][(tid & 31)*4] = b;
        __syncthreads();
        #pragma unroll
        for (int kk = 0; kk < 8; kk++) {
            float ra[8], rb[8];
            *(float4*)&ra[0] = *(const float4*)&As[kk][ty*8];
            *(float4*)&ra[4] = *(const float4*)&As[kk][ty*8+4];
            *(float4*)&rb[0] = *(const float4*)&Bs[kk][tx*8];
            *(float4*)&rb[4] = *(const float4*)&Bs[kk][tx*8+4];
            #pragma unroll
            for (int i = 0; i < 8; i++)
                #pragma unroll
                for (int j = 0; j < 8; j++)
                    acc[i][j] += ra[i]*rb[j];
        }
        __syncthreads();
    }
    #pragma unroll
    for (int i = 0; i < 8; i++) {
        int m = by*128 + ty*8 + i;
        int c0 = bx*128 + tx*8;
        float4 o0, o1;
        o0.x = acc[i][0] + bias[c0+0];
        o0.y = acc[i][1] + bias[c0+1];
        o0.z = acc[i][2] + bias[c0+2];
        o0.w = acc[i][3] + bias[c0+3];
        o1.x = acc[i][4] + bias[c0+4];
        o1.y = acc[i][5] + bias[c0+5];
        o1.z = acc[i][6] + bias[c0+6];
        o1.w = acc[i][7] + bias[c0+7];
        *(float4*)(Cout + (size_t)m*Nn + c0)     = o0;
        *(float4*)(Cout + (size_t)m*Nn + c0 + 4) = o1;
    }
}

// ---------------------------------------------------------------------------
extern "C" void kernel_launch(void* const* d_in, const int* in_sizes, int n_in,
                              void* d_out, int out_size)
{
    const float* x          = (const float*)d_in[0];
    const unsigned char* mask = (const unsigned char*)d_in[1];
    const float* pos_bias   = (const float*)d_in[2];
    const float* pareto     = (const float*)d_in[3];
    const float* Wqkv       = (const float*)d_in[4];
    const float* bqkv       = (const float*)d_in[5];
    const float* Wo         = (const float*)d_in[6];
    const float* bo         = (const float*)d_in[7];
    float* out              = (float*)d_out;

    (void)in_sizes; (void)n_in; (void)out_size;

    // 1) QKV projection (scatter epilogue into g_q/g_k/g_v)
    {
        dim3 grid(3*Hp*Dp/128, Bp*Np/128);   // 12 x 64
        gemm_qkv_kernel<<<grid, 256>>>(x, Wqkv, bqkv);
    }
    // 2) Top-64 key selection per (b,h,window)
    select_kernel<<<Bp*Hp*NWp, 256>>>(pareto, mask);
    // 3) Sparse windowed attention
    attn_kernel<<<Bp*Hp*NWp, 128>>>(pos_bias, mask);
    // 4) Output projection
    {
        dim3 grid(Cp/128, Bp*Np/128);        // 4 x 64
        gemm_out_kernel<<<grid, 256>>>(Wo, bo, out);
    }
}

// round 2
// speedup vs baseline: 1.5529x; 1.5529x over previous
#include <cuda_runtime.h>
#include <math.h>
#include <stdint.h>

// Problem constants
#define Bp 4
#define Np 2048
#define Cp 512
#define Hp 8
#define Dp 64
#define Wp 4
#define NWp 512
#define KEEP 64

// Scratch (device globals; no allocation allowed)
__device__ float g_q[Bp*Hp*Np*Dp];       // [B,H,N,D]
__device__ float g_k[Bp*Hp*Np*Dp];
__device__ float g_v[Bp*Hp*Np*Dp];
__device__ float g_attn[Bp*Np*Hp*Dp];    // [B,N,H*D]
__device__ int   g_idx[Bp*Hp*NWp*KEEP];  // [B,H,NW,64]

// ---------------------------------------------------------------------------
// tf32 helpers
// ---------------------------------------------------------------------------
__device__ __forceinline__ float to_tf32(float x) {
    unsigned u;
    asm("cvt.rna.tf32.f32 %0, %1;" : "=r"(u) : "f"(x));
    return __uint_as_float(u);
}

__device__ __forceinline__ void mma_tf32(float4& d,
    unsigned a0, unsigned a1, unsigned a2, unsigned a3,
    unsigned b0, unsigned b1)
{
    asm volatile(
        "mma.sync.aligned.m16n8k8.row.col.f32.tf32.tf32.f32 "
        "{%0,%1,%2,%3}, {%4,%5,%6,%7}, {%8,%9}, {%0,%1,%2,%3};\n"
        : "+f"(d.x), "+f"(d.y), "+f"(d.z), "+f"(d.w)
        : "r"(a0), "r"(a1), "r"(a2), "r"(a3), "r"(b0), "r"(b1));
}

// ---------------------------------------------------------------------------
// Unified tf32 tensor-core GEMM: C[M,Nn] = A[M,512] * B[512,Nn] + bias
// Tile 128x128x32, 256 threads (8 warps as 2x4), warp tile 64x32.
// EPI=0: A = x, epilogue scatters into g_q/g_k/g_v (qkv projection)
// EPI=1: A = g_attn, epilogue writes Cout (output projection)
// ---------------------------------------------------------------------------
template<int EPI>
__global__ __launch_bounds__(256) void gemm_tf32_kernel(
    const float* __restrict__ Ain,
    const float* __restrict__ Bw,
    const float* __restrict__ bias,
    float* __restrict__ Cout,
    int Nn)
{
    const int Kk = 512;
    __shared__ float As[128][36];   // pad 36: float4-aligned (36*4=144=9*16)
    __shared__ float Bs[32][132];   // pad 132: 132*4=528=33*16

    const float* A = (EPI == 0) ? Ain : (const float*)g_attn;

    int tid = threadIdx.x;
    int bx = blockIdx.x, by = blockIdx.y;
    int warp = tid >> 5, lane = tid & 31;
    int wm = warp & 1, wn = warp >> 1;      // 2 x 4 warp grid
    int gid = lane >> 2, tig = lane & 3;

    float4 acc[4][4];
    #pragma unroll
    for (int i = 0; i < 4; i++)
        #pragma unroll
        for (int j = 0; j < 4; j++) acc[i][j] = make_float4(0.f,0.f,0.f,0.f);

    float4 ra[4], rb[4];

    // prologue: load tile kt=0
    #pragma unroll
    for (int i = 0; i < 4; i++) {
        int f = tid + i*256;
        ra[i] = *(const float4*)(A + (size_t)(by*128 + (f>>3))*Kk + (f&7)*4);
        rb[i] = *(const float4*)(Bw + (size_t)(f>>5)*Nn + bx*128 + (f&31)*4);
    }

    for (int kt = 0; kt < 16; kt++) {
        // store current tile (tf32-converted)
        #pragma unroll
        for (int i = 0; i < 4; i++) {
            int f = tid + i*256;
            float4 a = ra[i], b = rb[i];
            a.x = to_tf32(a.x); a.y = to_tf32(a.y); a.z = to_tf32(a.z); a.w = to_tf32(a.w);
            b.x = to_tf32(b.x); b.y = to_tf32(b.y); b.z = to_tf32(b.z); b.w = to_tf32(b.w);
            *(float4*)&As[f>>3][(f&7)*4]  = a;
            *(float4*)&Bs[f>>5][(f&31)*4] = b;
        }
        __syncthreads();

        // prefetch next tile
        if (kt < 15) {
            int k0n = (kt+1)*32;
            #pragma unroll
            for (int i = 0; i < 4; i++) {
                int f = tid + i*256;
                ra[i] = *(const float4*)(A + (size_t)(by*128 + (f>>3))*Kk + k0n + (f&7)*4);
                rb[i] = *(const float4*)(Bw + (size_t)(k0n + (f>>5))*Nn + bx*128 + (f&31)*4);
            }
        }

        // compute on smem tile
        #pragma unroll
        for (int ks = 0; ks < 4; ks++) {
            int k0 = ks*8;
            unsigned af[4][4], bf[4][2];
            #pragma unroll
            for (int i = 0; i < 4; i++) {
                int r = wm*64 + i*16 + gid;
                af[i][0] = __float_as_uint(As[r  ][k0 + tig]);
                af[i][1] = __float_as_uint(As[r+8][k0 + tig]);
                af[i][2] = __float_as_uint(As[r  ][k0 + tig + 4]);
                af[i][3] = __float_as_uint(As[r+8][k0 + tig + 4]);
            }
            #pragma unroll
            for (int j = 0; j < 4; j++) {
                int c = wn*32 + j*8 + gid;
                bf[j][0] = __float_as_uint(Bs[k0 + tig    ][c]);
                bf[j][1] = __float_as_uint(Bs[k0 + tig + 4][c]);
            }
            #pragma unroll
            for (int i = 0; i < 4; i++)
                #pragma unroll
                for (int j = 0; j < 4; j++)
                    mma_tf32(acc[i][j], af[i][0], af[i][1], af[i][2], af[i][3],
                             bf[j][0], bf[j][1]);
        }
        __syncthreads();
    }

    // Epilogue
    #pragma unroll
    for (int i = 0; i < 4; i++) {
        int m0 = by*128 + wm*64 + i*16 + gid;
        #pragma unroll
        for (int j = 0; j < 4; j++) {
            int c0 = bx*128 + wn*32 + j*8 + tig*2;
            float4 d = acc[i][j];
            if (EPI == 0) {
                // scatter: c -> (hd, s): s=c%3, hd=c/3; m -> (b, n)
                float vals[4] = {d.x, d.y, d.z, d.w};
                #pragma unroll
                for (int e = 0; e < 4; e++) {
                    int c = c0 + (e & 1);
                    int m = m0 + (e >> 1)*8;
                    float v = vals[e] + bias[c];
                    int s = c % 3;
                    int hd = c / 3;
                    int h = hd >> 6, dd = hd & 63;
                    int b = m >> 11, nn = m & (Np-1);
                    float* dst = (s == 0) ? g_q : (s == 1) ? g_k : g_v;
                    dst[(((size_t)(b*Hp + h))*Np + nn)*Dp + dd] = v;
                }
            } else {
                float2 o0 = make_float2(d.x + bias[c0], d.y + bias[c0+1]);
                float2 o1 = make_float2(d.z + bias[c0], d.w + bias[c0+1]);
                *(float2*)(Cout + (size_t)m0*Nn + c0)       = o0;
                *(float2*)(Cout + (size_t)(m0+8)*Nn + c0)   = o1;
            }
        }
    }
}

// ---------------------------------------------------------------------------
// Block-wide inclusive scan (256 threads) via warp shuffles.
// warpSums must be shared unsigned[8].
// ---------------------------------------------------------------------------
__device__ __forceinline__ unsigned blockScanIncl(unsigned v, unsigned* warpSums, int t)
{
    int lane = t & 31, wid = t >> 5;
    #pragma unroll
    for (int off = 1; off < 32; off <<= 1) {
        unsigned n = __shfl_up_sync(0xffffffffu, v, off);
        if (lane >= off) v += n;
    }
    if (lane == 31) warpSums[wid] = v;
    __syncthreads();
    if (wid == 0) {
        unsigned s = (lane < 8) ? warpSums[lane] : 0u;
        #pragma unroll
        for (int off = 1; off < 8; off <<= 1) {
            unsigned n = __shfl_up_sync(0xffffffffu, s, off);
            if (lane >= off) s += n;
        }
        if (lane < 8) warpSums[lane] = s;
    }
    __syncthreads();
    if (wid > 0) v += warpSums[wid - 1];
    return v;
}

// ---------------------------------------------------------------------------
// Selection: per (b,h,nw), radix-select 64 smallest of noised[j], stable
// in-index-order emit -> indices come out already sorted ascending.
// ---------------------------------------------------------------------------
__global__ __launch_bounds__(256) void select_kernel(
    const float* __restrict__ pareto,        // [B,H,NW,N]
    const unsigned char* __restrict__ mask)  // [B,N] bool
{
    __shared__ unsigned int skey[2048];
    __shared__ unsigned int hist[256];
    __shared__ unsigned int warpSums[8];
    __shared__ unsigned int sPrefix, sR, sTot;

    int p = blockIdx.x;                   // (b*H + h)*NW + nw
    int nw = p & (NWp-1);
    int b  = p / (Hp*NWp);
    int t  = threadIdx.x;

    const float* prow = pareto + (size_t)p * Np;
    const unsigned char* mrow = mask + (size_t)b * Np;

    // Build order-preserving uint keys
    #pragma unroll
    for (int v = 0; v < 2; v++) {
        int j0 = t*8 + v*4;
        float4 nz = *(const float4*)(prow + j0);
        float noise[4] = {nz.x, nz.y, nz.z, nz.w};
        #pragma unroll
        for (int i = 0; i < 4; i++) {
            int j = j0 + i;
            int cj = j >> 2;
            float gridv = fabsf((float)(nw - cj));
            float val = gridv - noise[i];
            if (mrow[j]) val = 3.402823466e38f;
            unsigned ub = __float_as_uint(val);
            ub ^= (ub & 0x80000000u) ? 0xFFFFFFFFu : 0x80000000u;
            skey[j] = ub;
        }
    }

    // Radix select: find key of rank 64 (1-based) ascending
    unsigned prefix = 0;
    for (int pass = 3; pass >= 0; --pass) {
        hist[t] = 0;
        __syncthreads();
        unsigned r = (pass == 3) ? 64u : sR;
        unsigned hm = (pass == 3) ? 0u : (0xFFFFFFFFu << ((pass+1)*8));
        #pragma unroll
        for (int i = 0; i < 8; i++) {
            unsigned k = skey[t*8 + i];
            if ((k & hm) == prefix)
                atomicAdd(&hist[(k >> (pass*8)) & 0xFF], 1u);
        }
        __syncthreads();
        unsigned hv = hist[t];
        unsigned incl = blockScanIncl(hv, warpSums, t);
        unsigned excl = incl - hv;
        if (excl < r && r <= incl) {
            sPrefix = prefix | ((unsigned)t << (pass*8));
            sR = r - excl;
        }
        __syncthreads();
        prefix = sPrefix;
    }
    unsigned T = prefix;
    __syncthreads();

    // Stable keep-scan: count (<T) and (==T) per thread, packed block scan
    unsigned lessC = 0, eqC = 0;
    #pragma unroll
    for (int i = 0; i < 8; i++) {
        unsigned k = skey[t*8 + i];
        lessC += (k < T);
        eqC   += (k == T);
    }
    unsigned packed = lessC | (eqC << 16);
    unsigned incl = blockScanIncl(packed, warpSums, t);
    if (t == 255) sTot = incl;
    __syncthreads();
    unsigned lb = (incl & 0xFFFFu) - lessC;      // exclusive prefixes
    unsigned eb = (incl >> 16)     - eqC;
    unsigned totalLess = sTot & 0xFFFFu;
    unsigned rr = 64u - totalLess;               // tie quota

    int* oidx = g_idx + (size_t)p * KEEP;
    #pragma unroll
    for (int i = 0; i < 8; i++) {
        int j = t*8 + i;
        unsigned k = skey[j];
        if (k < T) {
            oidx[lb + min(eb, rr)] = j;
            lb++;
        } else if (k == T) {
            if (eb < rr) oidx[lb + eb] = j;
            eb++;
        }
    }
}

// ---------------------------------------------------------------------------
// Attention: one block per (b,h,nw); gather K/V rows, dots+pb, softmax, AV.
// ---------------------------------------------------------------------------
__global__ __launch_bounds__(128) void attn_kernel(
    const float* __restrict__ pos_bias,      // [H,N,N]
    const unsigned char* __restrict__ mask)  // [B,N]
{
    __shared__ int   sidx[KEEP];
    __shared__ float ks[KEEP][65];
    __shared__ float vs[KEEP][65];
    __shared__ float qs[Wp][Dp];
    __shared__ float sd[Wp][68];

    int p  = blockIdx.x;                 // (b*H + h)*NW + nw
    int nw = p & (NWp-1);
    int bh = p >> 9;                     // b*H + h
    int h  = bh & (Hp-1);
    int b  = bh >> 3;
    int t  = threadIdx.x;

    if (t < KEEP) sidx[t] = g_idx[(size_t)p * KEEP + t];
    if (t >= 64 && t < 128) {
        int d = t - 64;
        #pragma unroll
        for (int w = 0; w < Wp; w++)
            qs[w][d] = g_q[((size_t)bh*Np + nw*Wp + w)*Dp + d];
    }
    __syncthreads();

    // Gather K/V: 2 threads per key row (32 floats each)
    {
        int z = t >> 1, half = t & 1;
        int row = sidx[z];
        const float* kp = g_k + ((size_t)bh*Np + row)*Dp + half*32;
        const float* vp = g_v + ((size_t)bh*Np + row)*Dp + half*32;
        #pragma unroll
        for (int i = 0; i < 8; i++) {
            float4 kv = *(const float4*)(kp + i*4);
            int c = half*32 + i*4;
            ks[z][c+0] = kv.x; ks[z][c+1] = kv.y; ks[z][c+2] = kv.z; ks[z][c+3] = kv.w;
            float4 vv = *(const float4*)(vp + i*4);
            vs[z][c+0] = vv.x; vs[z][c+1] = vv.y; vs[z][c+2] = vv.z; vs[z][c+3] = vv.w;
        }
    }
    __syncthreads();

    // Dots + pos_bias + masking
    const float scale = 0.125f;  // D^-0.5
    #pragma unroll
    for (int pr = t; pr < Wp*KEEP; pr += 128) {
        int w = pr >> 6, z = pr & 63;
        float acc = 0.f;
        #pragma unroll
        for (int d = 0; d < Dp; d++) acc += qs[w][d] * ks[z][d];
        int key = sidx[z];
        float pb = pos_bias[((size_t)h*Np + nw*Wp + w)*Np + key];
        float val = acc*scale + pb;
        bool qm = mask[(size_t)b*Np + nw*Wp + w] != 0;
        bool km = mask[(size_t)b*Np + key] != 0;
        if (qm && km) val = -3.402823466e38f;
        sd[w][z] = val;
    }
    __syncthreads();

    // Softmax: warp w owns row w (64 entries, 2 per lane)
    {
        int w = t >> 5, lane = t & 31;
        float v0 = sd[w][lane], v1 = sd[w][lane+32];
        float m = fmaxf(v0, v1);
        #pragma unroll
        for (int off = 16; off > 0; off >>= 1)
            m = fmaxf(m, __shfl_xor_sync(0xffffffffu, m, off));
        float e0 = __expf(v0 - m), e1 = __expf(v1 - m);
        float s = e0 + e1;
        #pragma unroll
        for (int off = 16; off > 0; off >>= 1)
            s += __shfl_xor_sync(0xffffffffu, s, off);
        float inv = 1.f / s;
        sd[w][lane]    = e0*inv;
        sd[w][lane+32] = e1*inv;
    }
    __syncthreads();

    // AV: out[w][d] = sum_z attn[w][z] * v[z][d]
    #pragma unroll
    for (int pr = t; pr < Wp*Dp; pr += 128) {
        int w = pr >> 6, d = pr & 63;
        float acc = 0.f;
        #pragma unroll
        for (int z = 0; z < KEEP; z++) acc += sd[w][z] * vs[z][d];
        g_attn[((size_t)b*Np + nw*Wp + w)*(Hp*Dp) + h*Dp + d] = acc;
    }
}

// ---------------------------------------------------------------------------
extern "C" void kernel_launch(void* const* d_in, const int* in_sizes, int n_in,
                              void* d_out, int out_size)
{
    const float* x            = (const float*)d_in[0];
    const unsigned char* mask = (const unsigned char*)d_in[1];
    const float* pos_bias     = (const float*)d_in[2];
    const float* pareto       = (const float*)d_in[3];
    const float* Wqkv         = (const float*)d_in[4];
    const float* bqkv         = (const float*)d_in[5];
    const float* Wo           = (const float*)d_in[6];
    const float* bo           = (const float*)d_in[7];
    float* out                = (float*)d_out;

    (void)in_sizes; (void)n_in; (void)out_size;

    // 1) QKV projection (tf32 tensor cores, scatter epilogue into g_q/g_k/g_v)
    {
        dim3 grid(3*Hp*Dp/128, Bp*Np/128);   // 12 x 64
        gemm_tf32_kernel<0><<<grid, 256>>>(x, Wqkv, bqkv, nullptr, 3*Hp*Dp);
    }
    // 2) Top-64 key selection per (b,h,window)
    select_kernel<<<Bp*Hp*NWp, 256>>>(pareto, mask);
    // 3) Sparse windowed attention
    attn_kernel<<<Bp*Hp*NWp, 128>>>(pos_bias, mask);
    // 4) Output projection (tf32 tensor cores)
    {
        dim3 grid(Cp/128, Bp*Np/128);        // 4 x 64
        gemm_tf32_kernel<1><<<grid, 256>>>(nullptr, Wo, bo, out, Cp);
    }
}

// round 3
// speedup vs baseline: 1.8950x; 1.2203x over previous
#include <cuda_runtime.h>
#include <math.h>
#include <stdint.h>

// Problem constants
#define Bp 4
#define Np 2048
#define Cp 512
#define Hp 8
#define Dp 64
#define Wp 4
#define NWp 512
#define KEEP 64

// Scratch (device globals; no allocation allowed)
__device__ float g_q[Bp*Hp*Np*Dp];       // [B,H,N,D]
__device__ float g_k[Bp*Hp*Np*Dp];
__device__ float g_v[Bp*Hp*Np*Dp];
__device__ float g_attn[Bp*Np*Hp*Dp];    // [B,N,H*D]
__device__ int   g_idx[Bp*Hp*NWp*KEEP];  // [B,H,NW,64]

// ---------------------------------------------------------------------------
// tf32 helpers
// ---------------------------------------------------------------------------
__device__ __forceinline__ float to_tf32(float x) {
    unsigned u;
    asm("cvt.rna.tf32.f32 %0, %1;" : "=r"(u) : "f"(x));
    return __uint_as_float(u);
}

__device__ __forceinline__ void mma_tf32(float4& d,
    unsigned a0, unsigned a1, unsigned a2, unsigned a3,
    unsigned b0, unsigned b1)
{
    asm volatile(
        "mma.sync.aligned.m16n8k8.row.col.f32.tf32.tf32.f32 "
        "{%0,%1,%2,%3}, {%4,%5,%6,%7}, {%8,%9}, {%0,%1,%2,%3};\n"
        : "+f"(d.x), "+f"(d.y), "+f"(d.z), "+f"(d.w)
        : "r"(a0), "r"(a1), "r"(a2), "r"(a3), "r"(b0), "r"(b1));
}

// ---------------------------------------------------------------------------
// Unified tf32 tensor-core GEMM: C[M,Nn] = A[M,512] * B[512,Nn] + bias
// Tile 128x128x32, 256 threads (8 warps as 2x4), warp tile 64x32.
// EPI=0: A = x, epilogue scatters into g_q/g_k/g_v (qkv projection)
// EPI=1: A = g_attn, epilogue writes Cout (output projection)
// ---------------------------------------------------------------------------
template<int EPI>
__global__ __launch_bounds__(256) void gemm_tf32_kernel(
    const float* __restrict__ Ain,
    const float* __restrict__ Bw,
    const float* __restrict__ bias,
    float* __restrict__ Cout,
    int Nn)
{
    const int Kk = 512;
    __shared__ float As[128][36];
    __shared__ float Bs[32][132];

    const float* A = (EPI == 0) ? Ain : (const float*)g_attn;

    int tid = threadIdx.x;
    int bx = blockIdx.x, by = blockIdx.y;
    int warp = tid >> 5, lane = tid & 31;
    int wm = warp & 1, wn = warp >> 1;
    int gid = lane >> 2, tig = lane & 3;

    float4 acc[4][4];
    #pragma unroll
    for (int i = 0; i < 4; i++)
        #pragma unroll
        for (int j = 0; j < 4; j++) acc[i][j] = make_float4(0.f,0.f,0.f,0.f);

    float4 ra[4], rb[4];

    #pragma unroll
    for (int i = 0; i < 4; i++) {
        int f = tid + i*256;
        ra[i] = *(const float4*)(A + (size_t)(by*128 + (f>>3))*Kk + (f&7)*4);
        rb[i] = *(const float4*)(Bw + (size_t)(f>>5)*Nn + bx*128 + (f&31)*4);
    }

    for (int kt = 0; kt < 16; kt++) {
        #pragma unroll
        for (int i = 0; i < 4; i++) {
            int f = tid + i*256;
            float4 a = ra[i], b = rb[i];
            a.x = to_tf32(a.x); a.y = to_tf32(a.y); a.z = to_tf32(a.z); a.w = to_tf32(a.w);
            b.x = to_tf32(b.x); b.y = to_tf32(b.y); b.z = to_tf32(b.z); b.w = to_tf32(b.w);
            *(float4*)&As[f>>3][(f&7)*4]  = a;
            *(float4*)&Bs[f>>5][(f&31)*4] = b;
        }
        __syncthreads();

        if (kt < 15) {
            int k0n = (kt+1)*32;
            #pragma unroll
            for (int i = 0; i < 4; i++) {
                int f = tid + i*256;
                ra[i] = *(const float4*)(A + (size_t)(by*128 + (f>>3))*Kk + k0n + (f&7)*4);
                rb[i] = *(const float4*)(Bw + (size_t)(k0n + (f>>5))*Nn + bx*128 + (f&31)*4);
            }
        }

        #pragma unroll
        for (int ks = 0; ks < 4; ks++) {
            int k0 = ks*8;
            unsigned af[4][4], bf[4][2];
            #pragma unroll
            for (int i = 0; i < 4; i++) {
                int r = wm*64 + i*16 + gid;
                af[i][0] = __float_as_uint(As[r  ][k0 + tig]);
                af[i][1] = __float_as_uint(As[r+8][k0 + tig]);
                af[i][2] = __float_as_uint(As[r  ][k0 + tig + 4]);
                af[i][3] = __float_as_uint(As[r+8][k0 + tig + 4]);
            }
            #pragma unroll
            for (int j = 0; j < 4; j++) {
                int c = wn*32 + j*8 + gid;
                bf[j][0] = __float_as_uint(Bs[k0 + tig    ][c]);
                bf[j][1] = __float_as_uint(Bs[k0 + tig + 4][c]);
            }
            #pragma unroll
            for (int i = 0; i < 4; i++)
                #pragma unroll
                for (int j = 0; j < 4; j++)
                    mma_tf32(acc[i][j], af[i][0], af[i][1], af[i][2], af[i][3],
                             bf[j][0], bf[j][1]);
        }
        __syncthreads();
    }

    #pragma unroll
    for (int i = 0; i < 4; i++) {
        int m0 = by*128 + wm*64 + i*16 + gid;
        #pragma unroll
        for (int j = 0; j < 4; j++) {
            int c0 = bx*128 + wn*32 + j*8 + tig*2;
            float4 d = acc[i][j];
            if (EPI == 0) {
                float vals[4] = {d.x, d.y, d.z, d.w};
                #pragma unroll
                for (int e = 0; e < 4; e++) {
                    int c = c0 + (e & 1);
                    int m = m0 + (e >> 1)*8;
                    float v = vals[e] + bias[c];
                    int s = c % 3;
                    int hd = c / 3;
                    int h = hd >> 6, dd = hd & 63;
                    int b = m >> 11, nn = m & (Np-1);
                    float* dst = (s == 0) ? g_q : (s == 1) ? g_k : g_v;
                    dst[(((size_t)(b*Hp + h))*Np + nn)*Dp + dd] = v;
                }
            } else {
                float2 o0 = make_float2(d.x + bias[c0], d.y + bias[c0+1]);
                float2 o1 = make_float2(d.z + bias[c0], d.w + bias[c0+1]);
                *(float2*)(Cout + (size_t)m0*Nn + c0)       = o0;
                *(float2*)(Cout + (size_t)(m0+8)*Nn + c0)   = o1;
            }
        }
    }
}

// ---------------------------------------------------------------------------
// Block-wide inclusive scan (256 threads) via warp shuffles.
// ---------------------------------------------------------------------------
__device__ __forceinline__ unsigned blockScanIncl(unsigned v, unsigned* warpSums, int t)
{
    int lane = t & 31, wid = t >> 5;
    #pragma unroll
    for (int off = 1; off < 32; off <<= 1) {
        unsigned n = __shfl_up_sync(0xffffffffu, v, off);
        if (lane >= off) v += n;
    }
    if (lane == 31) warpSums[wid] = v;
    __syncthreads();
    if (wid == 0) {
        unsigned s = (lane < 8) ? warpSums[lane] : 0u;
        #pragma unroll
        for (int off = 1; off < 8; off <<= 1) {
            unsigned n = __shfl_up_sync(0xffffffffu, s, off);
            if (lane >= off) s += n;
        }
        if (lane < 8) warpSums[lane] = s;
    }
    __syncthreads();
    if (wid > 0) v += warpSums[wid - 1];
    return v;
}

// Find bin b over NB bins such that cum(hist[0..b)) < r <= cum(hist[0..b]).
// Writes sOut[0]=bin, sOut[1]=cumBefore. All 256 threads participate.
template<int NB>
__device__ __forceinline__ void findThresholdBin(
    const unsigned* hist, unsigned r, unsigned* warpSums, unsigned* sOut, int t)
{
    const int PER = NB / 256;
    unsigned loc[PER];
    unsigned s = 0;
    #pragma unroll
    for (int i = 0; i < PER; i++) { loc[i] = hist[t*PER + i]; s += loc[i]; }
    unsigned incl = blockScanIncl(s, warpSums, t);
    unsigned excl = incl - s;
    if (excl < r && r <= incl) {
        unsigned cum = excl;
        #pragma unroll
        for (int i = 0; i < PER; i++) {
            if (cum + loc[i] >= r) { sOut[0] = t*PER + i; sOut[1] = cum; break; }
            cum += loc[i];
        }
    }
    __syncthreads();
}

// ---------------------------------------------------------------------------
// Selection: per (b,h,nw), hierarchical radix-select (11/11/10 bits) of the
// 64 smallest noised keys; stable in-index-order emit -> sorted indices.
// ---------------------------------------------------------------------------
__global__ __launch_bounds__(256) void select_kernel(
    const float* __restrict__ pareto,        // [B,H,NW,N]
    const unsigned char* __restrict__ mask)  // [B,N] bool
{
    __shared__ unsigned hist[2048];
    __shared__ unsigned cand[2048];
    __shared__ unsigned warpSums[8];
    __shared__ unsigned sOut[2];
    __shared__ unsigned sCnt;
    __shared__ unsigned sE;

    int p = blockIdx.x;                   // (b*H + h)*NW + nw
    int nw = p & (NWp-1);
    int b  = p / (Hp*NWp);
    int t  = threadIdx.x;

    const float* prow = pareto + (size_t)p * Np;
    const unsigned char* mrow = mask + (size_t)b * Np;

    // Build order-preserving uint keys in registers (8 per thread, j = t*8+i)
    unsigned key[8];
    #pragma unroll
    for (int v = 0; v < 2; v++) {
        int j0 = t*8 + v*4;
        float4 nz = *(const float4*)(prow + j0);
        float noise[4] = {nz.x, nz.y, nz.z, nz.w};
        #pragma unroll
        for (int i = 0; i < 4; i++) {
            int j = j0 + i;
            int cj = j >> 2;
            float gridv = fabsf((float)(nw - cj));
            float val = gridv - noise[i];
            if (mrow[j]) val = 3.402823466e38f;
            unsigned ub = __float_as_uint(val);
            ub ^= (ub & 0x80000000u) ? 0xFFFFFFFFu : 0x80000000u;
            key[v*4 + i] = ub;
        }
    }

    // ---- Pass 1: top 11 bits, histogram over all 2048 keys ----
    #pragma unroll
    for (int i = 0; i < 8; i++) hist[t*8 + i] = 0;
    __syncthreads();
    #pragma unroll
    for (int i = 0; i < 8; i++)
        atomicAdd(&hist[key[i] >> 21], 1u);
    __syncthreads();

    unsigned r = 64;
    findThresholdBin<2048>(hist, r, warpSums, sOut, t);
    unsigned bin1 = sOut[0];
    r -= sOut[1];
    unsigned prefix = bin1 << 21;
    __syncthreads();

    // gather candidates (keys whose top 11 bits == bin1)
    if (t == 0) sCnt = 0;
    __syncthreads();
    #pragma unroll
    for (int i = 0; i < 8; i++)
        if ((key[i] >> 21) == bin1)
            cand[atomicAdd(&sCnt, 1u)] = key[i];
    __syncthreads();
    unsigned E = sCnt;

    // ---- Pass 2: bits [10,21) over candidate list ----
    {
        #pragma unroll
        for (int i = 0; i < 8; i++) hist[t*8 + i] = 0;
        // cache my slice of cand
        unsigned kk[8]; int n = 0;
        for (unsigned j = t; j < E; j += 256) kk[n++] = cand[j];
        __syncthreads();
        for (int i = 0; i < n; i++)
            atomicAdd(&hist[(kk[i] >> 10) & 0x7FFu], 1u);
        __syncthreads();
        findThresholdBin<2048>(hist, r, warpSums, sOut, t);
        unsigned bin2 = sOut[0];
        r -= sOut[1];
        prefix |= bin2 << 10;
        __syncthreads();
        if (t == 0) sCnt = 0;
        __syncthreads();
        for (int i = 0; i < n; i++)
            if (((kk[i] >> 10) & 0x7FFu) == bin2)
                cand[atomicAdd(&sCnt, 1u)] = kk[i];
        __syncthreads();
        E = sCnt;
    }

    // ---- Pass 3: bits [0,10) over candidate list (final, exact) ----
    {
        #pragma unroll
        for (int i = 0; i < 4; i++) hist[t*4 + i] = 0;
        unsigned kk[8]; int n = 0;
        for (unsigned j = t; j < E; j += 256) kk[n++] = cand[j];
        __syncthreads();
        for (int i = 0; i < n; i++)
            atomicAdd(&hist[kk[i] & 0x3FFu], 1u);
        __syncthreads();
        findThresholdBin<1024>(hist, r, warpSums, sOut, t);
        unsigned bin3 = sOut[0];
        r -= sOut[1];
        prefix |= bin3;
        __syncthreads();
    }

    unsigned T = prefix;     // exact rank-64 key value
    unsigned rr = r;         // tie quota among keys == T

    // Stable keep-scan: count (<T) and (==T) per thread, packed block scan
    unsigned lessC = 0, eqC = 0;
    #pragma unroll
    for (int i = 0; i < 8; i++) {
        lessC += (key[i] < T);
        eqC   += (key[i] == T);
    }
    unsigned packed = lessC | (eqC << 16);
    unsigned incl = blockScanIncl(packed, warpSums, t);
    unsigned lb = (incl & 0xFFFFu) - lessC;
    unsigned eb = (incl >> 16)     - eqC;

    int* oidx = g_idx + (size_t)p * KEEP;
    #pragma unroll
    for (int i = 0; i < 8; i++) {
        int j = t*8 + i;
        unsigned k = key[i];
        if (k < T) {
            oidx[lb + min(eb, rr)] = j;
            lb++;
        } else if (k == T) {
            if (eb < rr) oidx[lb + eb] = j;
            eb++;
        }
    }
}

// ---------------------------------------------------------------------------
// Attention: one block per (b,h,nw); 256 threads.
// ---------------------------------------------------------------------------
__global__ __launch_bounds__(256) void attn_kernel(
    const float* __restrict__ pos_bias,      // [H,N,N]
    const unsigned char* __restrict__ mask)  // [B,N]
{
    __shared__ int   sidx[KEEP];
    __shared__ float ks[KEEP][65];
    __shared__ float vs[KEEP][65];
    __shared__ float qs[Wp][Dp];
    __shared__ float sd[Wp][68];

    int p  = blockIdx.x;                 // (b*H + h)*NW + nw
    int nw = p & (NWp-1);
    int bh = p >> 9;                     // b*H + h
    int h  = bh & (Hp-1);
    int b  = bh >> 3;
    int t  = threadIdx.x;

    if (t < KEEP) sidx[t] = g_idx[(size_t)p * KEEP + t];
    {
        int w = t >> 6, d = t & 63;
        qs[w][d] = g_q[((size_t)bh*Np + nw*Wp + w)*Dp + d];
    }
    __syncthreads();

    // Gather K/V: 4 threads per key row (16 floats each)
    {
        int z = t >> 2, quar = t & 3;
        int row = sidx[z];
        const float* kp = g_k + ((size_t)bh*Np + row)*Dp + quar*16;
        const float* vp = g_v + ((size_t)bh*Np + row)*Dp + quar*16;
        #pragma unroll
        for (int i = 0; i < 4; i++) {
            float4 kv = *(const float4*)(kp + i*4);
            int c = quar*16 + i*4;
            ks[z][c+0] = kv.x; ks[z][c+1] = kv.y; ks[z][c+2] = kv.z; ks[z][c+3] = kv.w;
            float4 vv = *(const float4*)(vp + i*4);
            vs[z][c+0] = vv.x; vs[z][c+1] = vv.y; vs[z][c+2] = vv.z; vs[z][c+3] = vv.w;
        }
    }
    __syncthreads();

    // Dots + pos_bias + masking: one (w,z) pair per thread
    const float scale = 0.125f;  // D^-0.5
    {
        int w = t >> 6, z = t & 63;
        float acc = 0.f;
        #pragma unroll
        for (int d = 0; d < Dp; d++) acc += qs[w][d] * ks[z][d];
        int key = sidx[z];
        float pb = __ldg(pos_bias + ((size_t)h*Np + nw*Wp + w)*Np + key);
        float val = acc*scale + pb;
        bool qm = mask[(size_t)b*Np + nw*Wp + w] != 0;
        bool km = mask[(size_t)b*Np + key] != 0;
        if (qm && km) val = -3.402823466e38f;
        sd[w][z] = val;
    }
    __syncthreads();

    // Softmax: warp w (w<4) owns row w (64 entries, 2 per lane)
    if (t < 128) {
        int w = t >> 5, lane = t & 31;
        float v0 = sd[w][lane], v1 = sd[w][lane+32];
        float m = fmaxf(v0, v1);
        #pragma unroll
        for (int off = 16; off > 0; off >>= 1)
            m = fmaxf(m, __shfl_xor_sync(0xffffffffu, m, off));
        float e0 = __expf(v0 - m), e1 = __expf(v1 - m);
        float s = e0 + e1;
        #pragma unroll
        for (int off = 16; off > 0; off >>= 1)
            s += __shfl_xor_sync(0xffffffffu, s, off);
        float inv = 1.f / s;
        sd[w][lane]    = e0*inv;
        sd[w][lane+32] = e1*inv;
    }
    __syncthreads();

    // AV: one (w,d) per thread
    {
        int w = t >> 6, d = t & 63;
        float acc = 0.f;
        #pragma unroll
        for (int z = 0; z < KEEP; z++) acc += sd[w][z] * vs[z][d];
        g_attn[((size_t)b*Np + nw*Wp + w)*(Hp*Dp) + h*Dp + d] = acc;
    }
}

// ---------------------------------------------------------------------------
extern "C" void kernel_launch(void* const* d_in, const int* in_sizes, int n_in,
                              void* d_out, int out_size)
{
    const float* x            = (const float*)d_in[0];
    const unsigned char* mask = (const unsigned char*)d_in[1];
    const float* pos_bias     = (const float*)d_in[2];
    const float* pareto       = (const float*)d_in[3];
    const float* Wqkv         = (const float*)d_in[4];
    const float* bqkv         = (const float*)d_in[5];
    const float* Wo           = (const float*)d_in[6];
    const float* bo           = (const float*)d_in[7];
    float* out                = (float*)d_out;

    (void)in_sizes; (void)n_in; (void)out_size;

    {
        dim3 grid(3*Hp*Dp/128, Bp*Np/128);   // 12 x 64
        gemm_tf32_kernel<0><<<grid, 256>>>(x, Wqkv, bqkv, nullptr, 3*Hp*Dp);
    }
    select_kernel<<<Bp*Hp*NWp, 256>>>(pareto, mask);
    attn_kernel<<<Bp*Hp*NWp, 256>>>(pos_bias, mask);
    {
        dim3 grid(Cp/128, Bp*Np/128);        // 4 x 64
        gemm_tf32_kernel<1><<<grid, 256>>>(nullptr, Wo, bo, out, Cp);
    }
}

// round 4
// speedup vs baseline: 1.9301x; 1.0185x over previous
#include <cuda_runtime.h>
#include <math.h>
#include <stdint.h>

// Problem constants
#define Bp 4
#define Np 2048
#define Cp 512
#define Hp 8
#define Dp 64
#define Wp 4
#define NWp 512
#define KEEP 64

// Scratch (device globals; no allocation allowed)
__device__ float g_q[Bp*Hp*Np*Dp];       // [B,H,N,D]
__device__ float g_k[Bp*Hp*Np*Dp];
__device__ float g_v[Bp*Hp*Np*Dp];
__device__ float g_attn[Bp*Np*Hp*Dp];    // [B,N,H*D]
__device__ int   g_idx[Bp*Hp*NWp*KEEP];  // [B,H,NW,64]

// ---------------------------------------------------------------------------
// tf32 helpers
// ---------------------------------------------------------------------------
__device__ __forceinline__ float to_tf32(float x) {
    unsigned u;
    asm("cvt.rna.tf32.f32 %0, %1;" : "=r"(u) : "f"(x));
    return __uint_as_float(u);
}

__device__ __forceinline__ void mma_tf32(float4& d,
    unsigned a0, unsigned a1, unsigned a2, unsigned a3,
    unsigned b0, unsigned b1)
{
    asm volatile(
        "mma.sync.aligned.m16n8k8.row.col.f32.tf32.tf32.f32 "
        "{%0,%1,%2,%3}, {%4,%5,%6,%7}, {%8,%9}, {%0,%1,%2,%3};\n"
        : "+f"(d.x), "+f"(d.y), "+f"(d.z), "+f"(d.w)
        : "r"(a0), "r"(a1), "r"(a2), "r"(a3), "r"(b0), "r"(b1));
}

// ---------------------------------------------------------------------------
// Unified tf32 tensor-core GEMM: C[M,Nn] = A[M,512] * B[512,Nn] + bias
// ---------------------------------------------------------------------------
template<int EPI>
__global__ __launch_bounds__(256) void gemm_tf32_kernel(
    const float* __restrict__ Ain,
    const float* __restrict__ Bw,
    const float* __restrict__ bias,
    float* __restrict__ Cout,
    int Nn)
{
    const int Kk = 512;
    __shared__ float As[128][36];
    __shared__ float Bs[32][132];

    const float* A = (EPI == 0) ? Ain : (const float*)g_attn;

    int tid = threadIdx.x;
    int bx = blockIdx.x, by = blockIdx.y;
    int warp = tid >> 5, lane = tid & 31;
    int wm = warp & 1, wn = warp >> 1;
    int gid = lane >> 2, tig = lane & 3;

    float4 acc[4][4];
    #pragma unroll
    for (int i = 0; i < 4; i++)
        #pragma unroll
        for (int j = 0; j < 4; j++) acc[i][j] = make_float4(0.f,0.f,0.f,0.f);

    float4 ra[4], rb[4];

    #pragma unroll
    for (int i = 0; i < 4; i++) {
        int f = tid + i*256;
        ra[i] = *(const float4*)(A + (size_t)(by*128 + (f>>3))*Kk + (f&7)*4);
        rb[i] = *(const float4*)(Bw + (size_t)(f>>5)*Nn + bx*128 + (f&31)*4);
    }

    for (int kt = 0; kt < 16; kt++) {
        #pragma unroll
        for (int i = 0; i < 4; i++) {
            int f = tid + i*256;
            float4 a = ra[i], b = rb[i];
            a.x = to_tf32(a.x); a.y = to_tf32(a.y); a.z = to_tf32(a.z); a.w = to_tf32(a.w);
            b.x = to_tf32(b.x); b.y = to_tf32(b.y); b.z = to_tf32(b.z); b.w = to_tf32(b.w);
            *(float4*)&As[f>>3][(f&7)*4]  = a;
            *(float4*)&Bs[f>>5][(f&31)*4] = b;
        }
        __syncthreads();

        if (kt < 15) {
            int k0n = (kt+1)*32;
            #pragma unroll
            for (int i = 0; i < 4; i++) {
                int f = tid + i*256;
                ra[i] = *(const float4*)(A + (size_t)(by*128 + (f>>3))*Kk + k0n + (f&7)*4);
                rb[i] = *(const float4*)(Bw + (size_t)(k0n + (f>>5))*Nn + bx*128 + (f&31)*4);
            }
        }

        #pragma unroll
        for (int ks = 0; ks < 4; ks++) {
            int k0 = ks*8;
            unsigned af[4][4], bf[4][2];
            #pragma unroll
            for (int i = 0; i < 4; i++) {
                int r = wm*64 + i*16 + gid;
                af[i][0] = __float_as_uint(As[r  ][k0 + tig]);
                af[i][1] = __float_as_uint(As[r+8][k0 + tig]);
                af[i][2] = __float_as_uint(As[r  ][k0 + tig + 4]);
                af[i][3] = __float_as_uint(As[r+8][k0 + tig + 4]);
            }
            #pragma unroll
            for (int j = 0; j < 4; j++) {
                int c = wn*32 + j*8 + gid;
                bf[j][0] = __float_as_uint(Bs[k0 + tig    ][c]);
                bf[j][1] = __float_as_uint(Bs[k0 + tig + 4][c]);
            }
            #pragma unroll
            for (int i = 0; i < 4; i++)
                #pragma unroll
                for (int j = 0; j < 4; j++)
                    mma_tf32(acc[i][j], af[i][0], af[i][1], af[i][2], af[i][3],
                             bf[j][0], bf[j][1]);
        }
        __syncthreads();
    }

    #pragma unroll
    for (int i = 0; i < 4; i++) {
        int m0 = by*128 + wm*64 + i*16 + gid;
        #pragma unroll
        for (int j = 0; j < 4; j++) {
            int c0 = bx*128 + wn*32 + j*8 + tig*2;
            float4 d = acc[i][j];
            if (EPI == 0) {
                float vals[4] = {d.x, d.y, d.z, d.w};
                #pragma unroll
                for (int e = 0; e < 4; e++) {
                    int c = c0 + (e & 1);
                    int m = m0 + (e >> 1)*8;
                    float v = vals[e] + bias[c];
                    int s = c % 3;
                    int hd = c / 3;
                    int h = hd >> 6, dd = hd & 63;
                    int b = m >> 11, nn = m & (Np-1);
                    float* dst = (s == 0) ? g_q : (s == 1) ? g_k : g_v;
                    dst[(((size_t)(b*Hp + h))*Np + nn)*Dp + dd] = v;
                }
            } else {
                float2 o0 = make_float2(d.x + bias[c0], d.y + bias[c0+1]);
                float2 o1 = make_float2(d.z + bias[c0], d.w + bias[c0+1]);
                *(float2*)(Cout + (size_t)m0*Nn + c0)       = o0;
                *(float2*)(Cout + (size_t)(m0+8)*Nn + c0)   = o1;
            }
        }
    }
}

// ---------------------------------------------------------------------------
// Block-wide inclusive scan (256 threads) via warp shuffles.
// ---------------------------------------------------------------------------
__device__ __forceinline__ unsigned blockScanIncl(unsigned v, unsigned* warpSums, int t)
{
    int lane = t & 31, wid = t >> 5;
    #pragma unroll
    for (int off = 1; off < 32; off <<= 1) {
        unsigned n = __shfl_up_sync(0xffffffffu, v, off);
        if (lane >= off) v += n;
    }
    if (lane == 31) warpSums[wid] = v;
    __syncthreads();
    if (wid == 0) {
        unsigned s = (lane < 8) ? warpSums[lane] : 0u;
        #pragma unroll
        for (int off = 1; off < 8; off <<= 1) {
            unsigned n = __shfl_up_sync(0xffffffffu, s, off);
            if (lane >= off) s += n;
        }
        if (lane < 8) warpSums[lane] = s;
    }
    __syncthreads();
    if (wid > 0) v += warpSums[wid - 1];
    return v;
}

template<int NB>
__device__ __forceinline__ void findThresholdBin(
    const unsigned* hist, unsigned r, unsigned* warpSums, unsigned* sOut, int t)
{
    const int PER = NB / 256;
    unsigned loc[PER];
    unsigned s = 0;
    #pragma unroll
    for (int i = 0; i < PER; i++) { loc[i] = hist[t*PER + i]; s += loc[i]; }
    unsigned incl = blockScanIncl(s, warpSums, t);
    unsigned excl = incl - s;
    if (excl < r && r <= incl) {
        unsigned cum = excl;
        #pragma unroll
        for (int i = 0; i < PER; i++) {
            if (cum + loc[i] >= r) { sOut[0] = t*PER + i; sOut[1] = cum; break; }
            cum += loc[i];
        }
    }
    __syncthreads();
}

// ---------------------------------------------------------------------------
// Selection: hierarchical radix-select (11/11/10 bits), stable sorted emit.
// ---------------------------------------------------------------------------
__global__ __launch_bounds__(256) void select_kernel(
    const float* __restrict__ pareto,        // [B,H,NW,N]
    const unsigned char* __restrict__ mask)  // [B,N] bool
{
    __shared__ unsigned hist[2048];
    __shared__ unsigned cand[2048];
    __shared__ unsigned warpSums[8];
    __shared__ unsigned sOut[2];
    __shared__ unsigned sCnt;

    int p = blockIdx.x;
    int nw = p & (NWp-1);
    int b  = p / (Hp*NWp);
    int t  = threadIdx.x;

    const float* prow = pareto + (size_t)p * Np;
    const unsigned char* mrow = mask + (size_t)b * Np;

    unsigned key[8];
    #pragma unroll
    for (int v = 0; v < 2; v++) {
        int j0 = t*8 + v*4;
        float4 nz = *(const float4*)(prow + j0);
        float noise[4] = {nz.x, nz.y, nz.z, nz.w};
        #pragma unroll
        for (int i = 0; i < 4; i++) {
            int j = j0 + i;
            int cj = j >> 2;
            float gridv = fabsf((float)(nw - cj));
            float val = gridv - noise[i];
            if (mrow[j]) val = 3.402823466e38f;
            unsigned ub = __float_as_uint(val);
            ub ^= (ub & 0x80000000u) ? 0xFFFFFFFFu : 0x80000000u;
            key[v*4 + i] = ub;
        }
    }

    #pragma unroll
    for (int i = 0; i < 8; i++) hist[t*8 + i] = 0;
    __syncthreads();
    #pragma unroll
    for (int i = 0; i < 8; i++)
        atomicAdd(&hist[key[i] >> 21], 1u);
    __syncthreads();

    unsigned r = 64;
    findThresholdBin<2048>(hist, r, warpSums, sOut, t);
    unsigned bin1 = sOut[0];
    r -= sOut[1];
    unsigned prefix = bin1 << 21;
    __syncthreads();

    if (t == 0) sCnt = 0;
    __syncthreads();
    #pragma unroll
    for (int i = 0; i < 8; i++)
        if ((key[i] >> 21) == bin1)
            cand[atomicAdd(&sCnt, 1u)] = key[i];
    __syncthreads();
    unsigned E = sCnt;

    {
        #pragma unroll
        for (int i = 0; i < 8; i++) hist[t*8 + i] = 0;
        unsigned kk[8]; int n = 0;
        for (unsigned j = t; j < E; j += 256) kk[n++] = cand[j];
        __syncthreads();
        for (int i = 0; i < n; i++)
            atomicAdd(&hist[(kk[i] >> 10) & 0x7FFu], 1u);
        __syncthreads();
        findThresholdBin<2048>(hist, r, warpSums, sOut, t);
        unsigned bin2 = sOut[0];
        r -= sOut[1];
        prefix |= bin2 << 10;
        __syncthreads();
        if (t == 0) sCnt = 0;
        __syncthreads();
        for (int i = 0; i < n; i++)
            if (((kk[i] >> 10) & 0x7FFu) == bin2)
                cand[atomicAdd(&sCnt, 1u)] = kk[i];
        __syncthreads();
        E = sCnt;
    }

    {
        #pragma unroll
        for (int i = 0; i < 4; i++) hist[t*4 + i] = 0;
        unsigned kk[8]; int n = 0;
        for (unsigned j = t; j < E; j += 256) kk[n++] = cand[j];
        __syncthreads();
        for (int i = 0; i < n; i++)
            atomicAdd(&hist[kk[i] & 0x3FFu], 1u);
        __syncthreads();
        findThresholdBin<1024>(hist, r, warpSums, sOut, t);
        unsigned bin3 = sOut[0];
        r -= sOut[1];
        prefix |= bin3;
        __syncthreads();
    }

    unsigned T = prefix;
    unsigned rr = r;

    unsigned lessC = 0, eqC = 0;
    #pragma unroll
    for (int i = 0; i < 8; i++) {
        lessC += (key[i] < T);
        eqC   += (key[i] == T);
    }
    unsigned packed = lessC | (eqC << 16);
    unsigned incl = blockScanIncl(packed, warpSums, t);
    unsigned lb = (incl & 0xFFFFu) - lessC;
    unsigned eb = (incl >> 16)     - eqC;

    int* oidx = g_idx + (size_t)p * KEEP;
    #pragma unroll
    for (int i = 0; i < 8; i++) {
        int j = t*8 + i;
        unsigned k = key[i];
        if (k < T) {
            oidx[lb + min(eb, rr)] = j;
            lb++;
        } else if (k == T) {
            if (eb < rr) oidx[lb + eb] = j;
            eb++;
        }
    }
}

// ---------------------------------------------------------------------------
// Attention: one block per (b,h,nw); 256 threads. Pad-68 rows (16B aligned,
// quarter-warp conflict-free for float4). AV reads each vs element once.
// ---------------------------------------------------------------------------
#define PADR 68
__global__ __launch_bounds__(256) void attn_kernel(
    const float* __restrict__ pos_bias,      // [H,N,N]
    const unsigned char* __restrict__ mask)  // [B,N]
{
    __shared__ int   sidx[KEEP];
    __shared__ float ks[KEEP][PADR];
    __shared__ float vs[KEEP][PADR];
    __shared__ float qs[Wp][PADR];
    __shared__ float sd[Wp][PADR];
    __shared__ float partial[4][Wp][Dp];

    int p  = blockIdx.x;
    int nw = p & (NWp-1);
    int bh = p >> 9;
    int h  = bh & (Hp-1);
    int b  = bh >> 3;
    int t  = threadIdx.x;

    if (t < KEEP) sidx[t] = g_idx[(size_t)p * KEEP + t];
    {
        int w = t >> 6, d = t & 63;
        qs[w][d] = g_q[((size_t)bh*Np + nw*Wp + w)*Dp + d];
    }
    __syncthreads();

    // Gather K/V: 4 threads per key row (16 floats each)
    {
        int z = t >> 2, quar = t & 3;
        int row = sidx[z];
        const float* kp = g_k + ((size_t)bh*Np + row)*Dp + quar*16;
        const float* vp = g_v + ((size_t)bh*Np + row)*Dp + quar*16;
        #pragma unroll
        for (int i = 0; i < 4; i++) {
            int c = quar*16 + i*4;
            *(float4*)&ks[z][c] = *(const float4*)(kp + i*4);
            *(float4*)&vs[z][c] = *(const float4*)(vp + i*4);
        }
    }
    __syncthreads();

    // Dots + pos_bias + masking: one (w,z) pair per thread, float4 over d
    const float scale = 0.125f;
    {
        int w = t >> 6, z = t & 63;
        float acc = 0.f;
        #pragma unroll
        for (int i = 0; i < 16; i++) {
            float4 qv = *(const float4*)&qs[w][i*4];
            float4 kv = *(const float4*)&ks[z][i*4];
            acc += qv.x*kv.x + qv.y*kv.y + qv.z*kv.z + qv.w*kv.w;
        }
        int key = sidx[z];
        float pb = __ldg(pos_bias + ((size_t)h*Np + nw*Wp + w)*Np + key);
        float val = acc*scale + pb;
        bool qm = mask[(size_t)b*Np + nw*Wp + w] != 0;
        bool km = mask[(size_t)b*Np + key] != 0;
        if (qm && km) val = -3.402823466e38f;
        sd[w][z] = val;
    }
    __syncthreads();

    // Softmax: warp w (w<4) owns row w
    if (t < 128) {
        int w = t >> 5, lane = t & 31;
        float v0 = sd[w][lane], v1 = sd[w][lane+32];
        float m = fmaxf(v0, v1);
        #pragma unroll
        for (int off = 16; off > 0; off >>= 1)
            m = fmaxf(m, __shfl_xor_sync(0xffffffffu, m, off));
        float e0 = __expf(v0 - m), e1 = __expf(v1 - m);
        float s = e0 + e1;
        #pragma unroll
        for (int off = 16; off > 0; off >>= 1)
            s += __shfl_xor_sync(0xffffffffu, s, off);
        float inv = 1.f / s;
        sd[w][lane]    = e0*inv;
        sd[w][lane+32] = e1*inv;
    }
    __syncthreads();

    // AV phase 1: thread (g,d), g = z-group of 16; each vs element read once,
    // amortized over all 4 window rows.
    {
        int g = t >> 6, d = t & 63;
        float a0 = 0.f, a1 = 0.f, a2 = 0.f, a3 = 0.f;
        #pragma unroll
        for (int zi = 0; zi < 16; zi++) {
            int z = g*16 + zi;
            float vv = vs[z][d];
            a0 += sd[0][z] * vv;
            a1 += sd[1][z] * vv;
            a2 += sd[2][z] * vv;
            a3 += sd[3][z] * vv;
        }
        partial[g][0][d] = a0;
        partial[g][1][d] = a1;
        partial[g][2][d] = a2;
        partial[g][3][d] = a3;
    }
    __syncthreads();

    // AV phase 2: thread (w,d) reduces 4 partials, writes out
    {
        int w = t >> 6, d = t & 63;
        float acc = partial[0][w][d] + partial[1][w][d]
                  + partial[2][w][d] + partial[3][w][d];
        g_attn[((size_t)b*Np + nw*Wp + w)*(Hp*Dp) + h*Dp + d] = acc;
    }
}

// ---------------------------------------------------------------------------
extern "C" void kernel_launch(void* const* d_in, const int* in_sizes, int n_in,
                              void* d_out, int out_size)
{
    const float* x            = (const float*)d_in[0];
    const unsigned char* mask = (const unsigned char*)d_in[1];
    const float* pos_bias     = (const float*)d_in[2];
    const float* pareto       = (const float*)d_in[3];
    const float* Wqkv         = (const float*)d_in[4];
    const float* bqkv         = (const float*)d_in[5];
    const float* Wo           = (const float*)d_in[6];
    const float* bo           = (const float*)d_in[7];
    float* out                = (float*)d_out;

    (void)in_sizes; (void)n_in; (void)out_size;

    // Lazy one-time creation of side stream + events (happens on the first,
    // non-captured correctness call; only reused handles during capture).
    static cudaStream_t s2 = nullptr;
    static cudaEvent_t evFork = nullptr, evJoin = nullptr;
    if (s2 == nullptr) {
        cudaStreamCreateWithFlags(&s2, cudaStreamNonBlocking);
        cudaEventCreateWithFlags(&evFork, cudaEventDisableTiming);
        cudaEventCreateWithFlags(&evJoin, cudaEventDisableTiming);
    }

    // Fork: select (pareto/mask only) runs concurrently with the QKV GEMM.
    cudaEventRecord(evFork, 0);
    cudaStreamWaitEvent(s2, evFork, 0);
    select_kernel<<<Bp*Hp*NWp, 256, 0, s2>>>(pareto, mask);
    cudaEventRecord(evJoin, s2);

    {
        dim3 grid(3*Hp*Dp/128, Bp*Np/128);   // 12 x 64
        gemm_tf32_kernel<0><<<grid, 256>>>(x, Wqkv, bqkv, nullptr, 3*Hp*Dp);
    }

    // Join: attention needs both q/k/v and g_idx.
    cudaStreamWaitEvent(0, evJoin, 0);
    attn_kernel<<<Bp*Hp*NWp, 256>>>(pos_bias, mask);

    {
        dim3 grid(Cp/128, Bp*Np/128);        // 4 x 64
        gemm_tf32_kernel<1><<<grid, 256>>>(nullptr, Wo, bo, out, Cp);
    }
}

// round 5
// speedup vs baseline: 2.1871x; 1.1332x over previous
#include <cuda_runtime.h>
#include <math.h>
#include <stdint.h>

// Problem constants
#define Bp 4
#define Np 2048
#define Cp 512
#define Hp 8
#define Dp 64
#define Wp 4
#define NWp 512
#define KEEP 64

// Scratch (device globals; no allocation allowed)
__device__ float g_q[Bp*Np*Hp*Dp];       // [B,N,H,D]
__device__ float g_k[Bp*Np*Hp*Dp];
__device__ float g_v[Bp*Np*Hp*Dp];
__device__ float g_attn[Bp*Np*Hp*Dp];    // [B,N,H*D]
__device__ int   g_idx[Bp*Hp*NWp*KEEP];  // [B,H,NW,64]
__device__ float g_Wperm[Cp*3*Hp*Dp];    // Wqkv columns permuted to (s,h,d) order
__device__ float g_bperm[3*Hp*Dp];

// ---------------------------------------------------------------------------
// tf32 helpers
// ---------------------------------------------------------------------------
__device__ __forceinline__ float to_tf32(float x) {
    unsigned u;
    asm("cvt.rna.tf32.f32 %0, %1;" : "=r"(u) : "f"(x));
    return __uint_as_float(u);
}

__device__ __forceinline__ void mma_tf32(float4& d,
    unsigned a0, unsigned a1, unsigned a2, unsigned a3,
    unsigned b0, unsigned b1)
{
    asm volatile(
        "mma.sync.aligned.m16n8k8.row.col.f32.tf32.tf32.f32 "
        "{%0,%1,%2,%3}, {%4,%5,%6,%7}, {%8,%9}, {%0,%1,%2,%3};\n"
        : "+f"(d.x), "+f"(d.y), "+f"(d.z), "+f"(d.w)
        : "r"(a0), "r"(a1), "r"(a2), "r"(a3), "r"(b0), "r"(b1));
}

// ---------------------------------------------------------------------------
// Weight/bias column permutation: u = s*512 + h*64 + d  <-  c = hd*3 + s
// ---------------------------------------------------------------------------
__global__ __launch_bounds__(256) void permW_kernel(
    const float* __restrict__ Wqkv, const float* __restrict__ bqkv)
{
    int idx = blockIdx.x*256 + threadIdx.x;      // 0 .. 512*1536-1
    int u = idx % 1536;
    int k = idx / 1536;
    int s = u >> 9, hd = u & 511;
    g_Wperm[idx] = Wqkv[(size_t)k*1536 + hd*3 + s];
    if (idx < 1536) g_bperm[idx] = bqkv[(idx & 511)*3 + (idx >> 9)];
}

// ---------------------------------------------------------------------------
// tf32 tensor-core GEMM, double-buffered (one sync per k-tile).
// Tile 128x128x32, 256 threads, dynamic smem 2 stages.
// EPI=0: A=x, B=g_Wperm, Nn=1536; block bx -> s=bx>>2 array, coalesced stores
//        into g_q/g_k/g_v laid out [B,N,H,D].
// EPI=1: A=g_attn, B=Wo, Nn=512, writes Cout.
// ---------------------------------------------------------------------------
#define AS_STRIDE 36
#define BS_STRIDE 132
#define AS_STAGE (128*AS_STRIDE)     // 4608 floats
#define BS_STAGE (32*BS_STRIDE)      // 4224 floats
#define GEMM_SMEM ((2*AS_STAGE + 2*BS_STAGE)*4)  // 70656 bytes

template<int EPI>
__global__ __launch_bounds__(256, 2) void gemm_tf32_kernel(
    const float* __restrict__ Ain,
    const float* __restrict__ BwIn,
    const float* __restrict__ biasIn,
    float* __restrict__ Cout,
    int Nn)
{
    extern __shared__ float smem[];
    float* AsB = smem;                 // [2][128][36]
    float* BsB = smem + 2*AS_STAGE;    // [2][32][132]

    const int Kk = 512;
    const float* A    = (EPI == 0) ? Ain : (const float*)g_attn;
    const float* Bw   = (EPI == 0) ? (const float*)g_Wperm : BwIn;
    const float* bias = (EPI == 0) ? (const float*)g_bperm : biasIn;

    int tid = threadIdx.x;
    int bx = blockIdx.x, by = blockIdx.y;
    int warp = tid >> 5, lane = tid & 31;
    int wm = warp & 1, wn = warp >> 1;
    int gid = lane >> 2, tig = lane & 3;

    float4 acc[4][4];
    #pragma unroll
    for (int i = 0; i < 4; i++)
        #pragma unroll
        for (int j = 0; j < 4; j++) acc[i][j] = make_float4(0.f,0.f,0.f,0.f);

    float4 ra[4], rb[4];

    // load tile 0
    #pragma unroll
    for (int i = 0; i < 4; i++) {
        int f = tid + i*256;
        ra[i] = *(const float4*)(A + (size_t)(by*128 + (f>>3))*Kk + (f&7)*4);
        rb[i] = *(const float4*)(Bw + (size_t)(f>>5)*Nn + bx*128 + (f&31)*4);
    }
    // store stage 0
    #pragma unroll
    for (int i = 0; i < 4; i++) {
        int f = tid + i*256;
        float4 a = ra[i], b = rb[i];
        a.x = to_tf32(a.x); a.y = to_tf32(a.y); a.z = to_tf32(a.z); a.w = to_tf32(a.w);
        b.x = to_tf32(b.x); b.y = to_tf32(b.y); b.z = to_tf32(b.z); b.w = to_tf32(b.w);
        *(float4*)&AsB[(f>>3)*AS_STRIDE + (f&7)*4]  = a;
        *(float4*)&BsB[(f>>5)*BS_STRIDE + (f&31)*4] = b;
    }
    __syncthreads();

    for (int kt = 0; kt < 16; kt++) {
        int cur = kt & 1;
        const float* Asc = AsB + cur*AS_STAGE;
        const float* Bsc = BsB + cur*BS_STAGE;

        // issue loads for next tile (in flight during compute)
        if (kt < 15) {
            int k0n = (kt+1)*32;
            #pragma unroll
            for (int i = 0; i < 4; i++) {
                int f = tid + i*256;
                ra[i] = *(const float4*)(A + (size_t)(by*128 + (f>>3))*Kk + k0n + (f&7)*4);
                rb[i] = *(const float4*)(Bw + (size_t)(k0n + (f>>5))*Nn + bx*128 + (f&31)*4);
            }
        }

        // compute on current stage
        #pragma unroll
        for (int ks = 0; ks < 4; ks++) {
            int k0 = ks*8;
            unsigned af[4][4], bf[4][2];
            #pragma unroll
            for (int i = 0; i < 4; i++) {
                int r = wm*64 + i*16 + gid;
                af[i][0] = __float_as_uint(Asc[ r    *AS_STRIDE + k0 + tig]);
                af[i][1] = __float_as_uint(Asc[(r+8)*AS_STRIDE + k0 + tig]);
                af[i][2] = __float_as_uint(Asc[ r    *AS_STRIDE + k0 + tig + 4]);
                af[i][3] = __float_as_uint(Asc[(r+8)*AS_STRIDE + k0 + tig + 4]);
            }
            #pragma unroll
            for (int j = 0; j < 4; j++) {
                int c = wn*32 + j*8 + gid;
                bf[j][0] = __float_as_uint(Bsc[(k0 + tig    )*BS_STRIDE + c]);
                bf[j][1] = __float_as_uint(Bsc[(k0 + tig + 4)*BS_STRIDE + c]);
            }
            #pragma unroll
            for (int i = 0; i < 4; i++)
                #pragma unroll
                for (int j = 0; j < 4; j++)
                    mma_tf32(acc[i][j], af[i][0], af[i][1], af[i][2], af[i][3],
                             bf[j][0], bf[j][1]);
        }

        // store next tile into the other stage
        if (kt < 15) {
            float* Asn = AsB + (cur^1)*AS_STAGE;
            float* Bsn = BsB + (cur^1)*BS_STAGE;
            #pragma unroll
            for (int i = 0; i < 4; i++) {
                int f = tid + i*256;
                float4 a = ra[i], b = rb[i];
                a.x = to_tf32(a.x); a.y = to_tf32(a.y); a.z = to_tf32(a.z); a.w = to_tf32(a.w);
                b.x = to_tf32(b.x); b.y = to_tf32(b.y); b.z = to_tf32(b.z); b.w = to_tf32(b.w);
                *(float4*)&Asn[(f>>3)*AS_STRIDE + (f&7)*4]  = a;
                *(float4*)&Bsn[(f>>5)*BS_STRIDE + (f&31)*4] = b;
            }
        }
        __syncthreads();
    }

    // Epilogue: both paths are coalesced float2 stores
    float* dst;
    int colBase, rowStride;
    if (EPI == 0) {
        int s = bx >> 2;
        dst = (s == 0) ? g_q : (s == 1) ? g_k : g_v;
        colBase = (bx & 3)*128;
        rowStride = 512;
    } else {
        dst = Cout;
        colBase = bx*128;
        rowStride = Nn;
    }
    #pragma unroll
    for (int i = 0; i < 4; i++) {
        int m0 = by*128 + wm*64 + i*16 + gid;
        #pragma unroll
        for (int j = 0; j < 4; j++) {
            int cl = wn*32 + j*8 + tig*2;                  // local col in [0,128)
            float bz0 = bias[(EPI==0 ? bx*128 : bx*128) + cl];
            float bz1 = bias[(EPI==0 ? bx*128 : bx*128) + cl + 1];
            float4 d = acc[i][j];
            float2 o0 = make_float2(d.x + bz0, d.y + bz1);
            float2 o1 = make_float2(d.z + bz0, d.w + bz1);
            *(float2*)(dst + (size_t)m0*rowStride + colBase + cl)     = o0;
            *(float2*)(dst + (size_t)(m0+8)*rowStride + colBase + cl) = o1;
        }
    }
}

// ---------------------------------------------------------------------------
// Block-wide inclusive scan (256 threads) via warp shuffles.
// ---------------------------------------------------------------------------
__device__ __forceinline__ unsigned blockScanIncl(unsigned v, unsigned* warpSums, int t)
{
    int lane = t & 31, wid = t >> 5;
    #pragma unroll
    for (int off = 1; off < 32; off <<= 1) {
        unsigned n = __shfl_up_sync(0xffffffffu, v, off);
        if (lane >= off) v += n;
    }
    if (lane == 31) warpSums[wid] = v;
    __syncthreads();
    if (wid == 0) {
        unsigned s = (lane < 8) ? warpSums[lane] : 0u;
        #pragma unroll
        for (int off = 1; off < 8; off <<= 1) {
            unsigned n = __shfl_up_sync(0xffffffffu, s, off);
            if (lane >= off) s += n;
        }
        if (lane < 8) warpSums[lane] = s;
    }
    __syncthreads();
    if (wid > 0) v += warpSums[wid - 1];
    return v;
}

template<int NB>
__device__ __forceinline__ void findThresholdBin(
    const unsigned* hist, unsigned r, unsigned* warpSums, unsigned* sOut, int t)
{
    const int PER = NB / 256;
    unsigned loc[PER];
    unsigned s = 0;
    #pragma unroll
    for (int i = 0; i < PER; i++) { loc[i] = hist[t*PER + i]; s += loc[i]; }
    unsigned incl = blockScanIncl(s, warpSums, t);
    unsigned excl = incl - s;
    if (excl < r && r <= incl) {
        unsigned cum = excl;
        #pragma unroll
        for (int i = 0; i < PER; i++) {
            if (cum + loc[i] >= r) { sOut[0] = t*PER + i; sOut[1] = cum; break; }
            cum += loc[i];
        }
    }
    __syncthreads();
}

// ---------------------------------------------------------------------------
// Selection: hierarchical radix-select (11/11/10 bits), stable sorted emit.
// ---------------------------------------------------------------------------
__global__ __launch_bounds__(256) void select_kernel(
    const float* __restrict__ pareto,        // [B,H,NW,N]
    const unsigned char* __restrict__ mask)  // [B,N] bool
{
    __shared__ unsigned hist[2048];
    __shared__ unsigned cand[2048];
    __shared__ unsigned warpSums[8];
    __shared__ unsigned sOut[2];
    __shared__ unsigned sCnt;

    int p = blockIdx.x;
    int nw = p & (NWp-1);
    int b  = p / (Hp*NWp);
    int t  = threadIdx.x;

    const float* prow = pareto + (size_t)p * Np;
    const unsigned char* mrow = mask + (size_t)b * Np;

    unsigned key[8];
    #pragma unroll
    for (int v = 0; v < 2; v++) {
        int j0 = t*8 + v*4;
        float4 nz = *(const float4*)(prow + j0);
        float noise[4] = {nz.x, nz.y, nz.z, nz.w};
        #pragma unroll
        for (int i = 0; i < 4; i++) {
            int j = j0 + i;
            int cj = j >> 2;
            float gridv = fabsf((float)(nw - cj));
            float val = gridv - noise[i];
            if (mrow[j]) val = 3.402823466e38f;
            unsigned ub = __float_as_uint(val);
            ub ^= (ub & 0x80000000u) ? 0xFFFFFFFFu : 0x80000000u;
            key[v*4 + i] = ub;
        }
    }

    #pragma unroll
    for (int i = 0; i < 8; i++) hist[t*8 + i] = 0;
    __syncthreads();
    #pragma unroll
    for (int i = 0; i < 8; i++)
        atomicAdd(&hist[key[i] >> 21], 1u);
    __syncthreads();

    unsigned r = 64;
    findThresholdBin<2048>(hist, r, warpSums, sOut, t);
    unsigned bin1 = sOut[0];
    r -= sOut[1];
    unsigned prefix = bin1 << 21;
    __syncthreads();

    if (t == 0) sCnt = 0;
    __syncthreads();
    #pragma unroll
    for (int i = 0; i < 8; i++)
        if ((key[i] >> 21) == bin1)
            cand[atomicAdd(&sCnt, 1u)] = key[i];
    __syncthreads();
    unsigned E = sCnt;

    {
        #pragma unroll
        for (int i = 0; i < 8; i++) hist[t*8 + i] = 0;
        unsigned kk[8]; int n = 0;
        for (unsigned j = t; j < E; j += 256) kk[n++] = cand[j];
        __syncthreads();
        for (int i = 0; i < n; i++)
            atomicAdd(&hist[(kk[i] >> 10) & 0x7FFu], 1u);
        __syncthreads();
        findThresholdBin<2048>(hist, r, warpSums, sOut, t);
        unsigned bin2 = sOut[0];
        r -= sOut[1];
        prefix |= bin2 << 10;
        __syncthreads();
        if (t == 0) sCnt = 0;
        __syncthreads();
        for (int i = 0; i < n; i++)
            if (((kk[i] >> 10) & 0x7FFu) == bin2)
                cand[atomicAdd(&sCnt, 1u)] = kk[i];
        __syncthreads();
        E = sCnt;
    }

    {
        #pragma unroll
        for (int i = 0; i < 4; i++) hist[t*4 + i] = 0;
        unsigned kk[8]; int n = 0;
        for (unsigned j = t; j < E; j += 256) kk[n++] = cand[j];
        __syncthreads();
        for (int i = 0; i < n; i++)
            atomicAdd(&hist[kk[i] & 0x3FFu], 1u);
        __syncthreads();
        findThresholdBin<1024>(hist, r, warpSums, sOut, t);
        unsigned bin3 = sOut[0];
        r -= sOut[1];
        prefix |= bin3;
        __syncthreads();
    }

    unsigned T = prefix;
    unsigned rr = r;

    unsigned lessC = 0, eqC = 0;
    #pragma unroll
    for (int i = 0; i < 8; i++) {
        lessC += (key[i] < T);
        eqC   += (key[i] == T);
    }
    unsigned packed = lessC | (eqC << 16);
    unsigned incl = blockScanIncl(packed, warpSums, t);
    unsigned lb = (incl & 0xFFFFu) - lessC;
    unsigned eb = (incl >> 16)     - eqC;

    int* oidx = g_idx + (size_t)p * KEEP;
    #pragma unroll
    for (int i = 0; i < 8; i++) {
        int j = t*8 + i;
        unsigned k = key[i];
        if (k < T) {
            oidx[lb + min(eb, rr)] = j;
            lb++;
        } else if (k == T) {
            if (eb < rr) oidx[lb + eb] = j;
            eb++;
        }
    }
}

// ---------------------------------------------------------------------------
// Attention: one block per (b,h,nw); 256 threads. q/k/v in [B,N,H,D].
// ---------------------------------------------------------------------------
#define PADR 68
__global__ __launch_bounds__(256) void attn_kernel(
    const float* __restrict__ pos_bias,      // [H,N,N]
    const unsigned char* __restrict__ mask)  // [B,N]
{
    __shared__ int   sidx[KEEP];
    __shared__ float ks[KEEP][PADR];
    __shared__ float vs[KEEP][PADR];
    __shared__ float qs[Wp][PADR];
    __shared__ float sd[Wp][PADR];
    __shared__ float partial[4][Wp][Dp];

    int p  = blockIdx.x;
    int nw = p & (NWp-1);
    int bh = p >> 9;
    int h  = bh & (Hp-1);
    int b  = bh >> 3;
    int t  = threadIdx.x;

    if (t < KEEP) sidx[t] = g_idx[(size_t)p * KEEP + t];
    {
        int w = t >> 6, d = t & 63;
        qs[w][d] = g_q[((size_t)(b*Np + nw*Wp + w)*Hp + h)*Dp + d];
    }
    __syncthreads();

    // Gather K/V: 4 threads per key row (16 floats each)
    {
        int z = t >> 2, quar = t & 3;
        int row = sidx[z];
        const float* kp = g_k + ((size_t)(b*Np + row)*Hp + h)*Dp + quar*16;
        const float* vp = g_v + ((size_t)(b*Np + row)*Hp + h)*Dp + quar*16;
        #pragma unroll
        for (int i = 0; i < 4; i++) {
            int c = quar*16 + i*4;
            *(float4*)&ks[z][c] = *(const float4*)(kp + i*4);
            *(float4*)&vs[z][c] = *(const float4*)(vp + i*4);
        }
    }
    __syncthreads();

    // Dots + pos_bias + masking: one (w,z) pair per thread.
    // pb/mask loads issued BEFORE the dot loop (latency overlap).
    const float scale = 0.125f;
    {
        int w = t >> 6, z = t & 63;
        int key = sidx[z];
        float pb = __ldg(pos_bias + ((size_t)h*Np + nw*Wp + w)*Np + key);
        bool qm = mask[(size_t)b*Np + nw*Wp + w] != 0;
        bool km = mask[(size_t)b*Np + key] != 0;
        float acc = 0.f;
        #pragma unroll
        for (int i = 0; i < 16; i++) {
            float4 qv = *(const float4*)&qs[w][i*4];
            float4 kv = *(const float4*)&ks[z][i*4];
            acc += qv.x*kv.x + qv.y*kv.y + qv.z*kv.z + qv.w*kv.w;
        }
        float val = acc*scale + pb;
        if (qm && km) val = -3.402823466e38f;
        sd[w][z] = val;
    }
    __syncthreads();

    // Softmax: warp w (w<4) owns row w
    if (t < 128) {
        int w = t >> 5, lane = t & 31;
        float v0 = sd[w][lane], v1 = sd[w][lane+32];
        float m = fmaxf(v0, v1);
        #pragma unroll
        for (int off = 16; off > 0; off >>= 1)
            m = fmaxf(m, __shfl_xor_sync(0xffffffffu, m, off));
        float e0 = __expf(v0 - m), e1 = __expf(v1 - m);
        float s = e0 + e1;
        #pragma unroll
        for (int off = 16; off > 0; off >>= 1)
            s += __shfl_xor_sync(0xffffffffu, s, off);
        float inv = 1.f / s;
        sd[w][lane]    = e0*inv;
        sd[w][lane+32] = e1*inv;
    }
    __syncthreads();

    // AV phase 1: thread (g,d), g = z-group of 16; each vs element read once
    {
        int g = t >> 6, d = t & 63;
        float a0 = 0.f, a1 = 0.f, a2 = 0.f, a3 = 0.f;
        #pragma unroll
        for (int zi = 0; zi < 16; zi++) {
            int z = g*16 + zi;
            float vv = vs[z][d];
            a0 += sd[0][z] * vv;
            a1 += sd[1][z] * vv;
            a2 += sd[2][z] * vv;
            a3 += sd[3][z] * vv;
        }
        partial[g][0][d] = a0;
        partial[g][1][d] = a1;
        partial[g][2][d] = a2;
        partial[g][3][d] = a3;
    }
    __syncthreads();

    // AV phase 2: reduce 4 partials, write out
    {
        int w = t >> 6, d = t & 63;
        float acc = partial[0][w][d] + partial[1][w][d]
                  + partial[2][w][d] + partial[3][w][d];
        g_attn[((size_t)b*Np + nw*Wp + w)*(Hp*Dp) + h*Dp + d] = acc;
    }
}

// ---------------------------------------------------------------------------
extern "C" void kernel_launch(void* const* d_in, const int* in_sizes, int n_in,
                              void* d_out, int out_size)
{
    const float* x            = (const float*)d_in[0];
    const unsigned char* mask = (const unsigned char*)d_in[1];
    const float* pos_bias     = (const float*)d_in[2];
    const float* pareto       = (const float*)d_in[3];
    const float* Wqkv         = (const float*)d_in[4];
    const float* bqkv         = (const float*)d_in[5];
    const float* Wo           = (const float*)d_in[6];
    const float* bo           = (const float*)d_in[7];
    float* out                = (float*)d_out;

    (void)in_sizes; (void)n_in; (void)out_size;

    // One-time setup on the first (non-captured) correctness call.
    static cudaStream_t s2 = nullptr;
    static cudaEvent_t evFork = nullptr, evPerm = nullptr, evJoin = nullptr;
    if (s2 == nullptr) {
        cudaStreamCreateWithFlags(&s2, cudaStreamNonBlocking);
        cudaEventCreateWithFlags(&evFork, cudaEventDisableTiming);
        cudaEventCreateWithFlags(&evPerm, cudaEventDisableTiming);
        cudaEventCreateWithFlags(&evJoin, cudaEventDisableTiming);
        cudaFuncSetAttribute(gemm_tf32_kernel<0>,
            cudaFuncAttributeMaxDynamicSharedMemorySize, GEMM_SMEM);
        cudaFuncSetAttribute(gemm_tf32_kernel<1>,
            cudaFuncAttributeMaxDynamicSharedMemorySize, GEMM_SMEM);
    }

    // Fork side stream: weight permute, then selection.
    cudaEventRecord(evFork, 0);
    cudaStreamWaitEvent(s2, evFork, 0);
    permW_kernel<<<(Cp*3*Hp*Dp)/256, 256, 0, s2>>>(Wqkv, bqkv);
    cudaEventRecord(evPerm, s2);
    select_kernel<<<Bp*Hp*NWp, 256, 0, s2>>>(pareto, mask);
    cudaEventRecord(evJoin, s2);

    // QKV GEMM (needs permuted weights).
    cudaStreamWaitEvent(0, evPerm, 0);
    {
        dim3 grid(3*Hp*Dp/128, Bp*Np/128);   // 12 x 64
        gemm_tf32_kernel<0><<<grid, 256, GEMM_SMEM>>>(x, nullptr, nullptr, nullptr, 3*Hp*Dp);
    }

    // Attention (needs q/k/v and g_idx).
    cudaStreamWaitEvent(0, evJoin, 0);
    attn_kernel<<<Bp*Hp*NWp, 256>>>(pos_bias, mask);

    // Output projection.
    {
        dim3 grid(Cp/128, Bp*Np/128);        // 4 x 64
        gemm_tf32_kernel<1><<<grid, 256, GEMM_SMEM>>>(nullptr, Wo, bo, out, Cp);
    }
}